// round 15
// baseline (speedup 1.0000x reference)
#include <cuda_runtime.h>
#include <cuda_bf16.h>
#include <math.h>
#include <stdint.h>

#define BB 64
#define TT 512
#define VV 256
#define MM 1024
#define G4 4096

// ---- static device scratch (no cudaMalloc allowed) ----
__device__ float g_pre[(size_t)BB * TT * G4];    // 512 MB pre-activations
__device__ float g_cfin[2 * BB * MM];
__device__ float g_hfin[2 * BB * MM];
__device__ unsigned g_bar_count;
__device__ unsigned g_bar_gen;
// split-bf16 activation sequence (x splits, then h0 splits, then h1 splits)
__device__ __nv_bfloat16 g_Ahi[(size_t)BB * TT * MM];
__device__ __nv_bfloat16 g_Alo[(size_t)BB * TT * MM];
__device__ __nv_bfloat16 g_h0h[BB * MM], g_h0l[BB * MM];
// transposed split weights
__device__ __nv_bfloat16 g_Wt0hi[G4 * VV], g_Wt0lo[G4 * VV];
__device__ __nv_bfloat16 g_Wt1hi[(size_t)G4 * MM], g_Wt1lo[(size_t)G4 * MM];
__device__ __nv_bfloat16 g_WtOhi[VV * MM], g_WtOlo[VV * MM];
__device__ __nv_bfloat16 g_Wh0hi[(size_t)G4 * MM], g_Wh0lo[(size_t)G4 * MM];
__device__ __nv_bfloat16 g_Wh1hi[(size_t)G4 * MM], g_Wh1lo[(size_t)G4 * MM];

__device__ __forceinline__ float sigmoidf_(float x) {
    return 1.0f / (1.0f + __expf(-x));
}

__device__ __forceinline__ uint32_t smem_u32(const void* p) {
    uint32_t a;
    asm("{ .reg .u64 t; cvta.to.shared.u64 t, %1; cvt.u32.u64 %0, t; }"
        : "=r"(a) : "l"(p));
    return a;
}

// ---------------- prep kernels ----------------
__global__ void split_kernel(const float* __restrict__ in,
                             __nv_bfloat16* __restrict__ hi,
                             __nv_bfloat16* __restrict__ lo, size_t n) {
    size_t i = (size_t)blockIdx.x * blockDim.x + threadIdx.x;
    if (i < n) {
        float v = in[i];
        __nv_bfloat16 h = __float2bfloat16_rn(v);
        hi[i] = h;
        lo[i] = __float2bfloat16_rn(v - __bfloat162float(h));
    }
}

__global__ void split_state_h(const float* __restrict__ state,
                              __nv_bfloat16* __restrict__ hh,
                              __nv_bfloat16* __restrict__ hl) {
    int i = blockIdx.x * blockDim.x + threadIdx.x;
    if (i < BB * MM) {
        int b = i >> 10, m = i & 1023;
        float v = state[(size_t)b * (2 * MM) + MM + m];
        __nv_bfloat16 h = __float2bfloat16_rn(v);
        hh[i] = h;
        hl[i] = __float2bfloat16_rn(v - __bfloat162float(h));
    }
}

// W[k][ldin] (first K rows, N cols) -> T[n][K] hi/lo
__global__ void transpose_split_kernel(const float* __restrict__ W, int ldin,
                                       __nv_bfloat16* __restrict__ Thi,
                                       __nv_bfloat16* __restrict__ Tlo,
                                       int K, int N) {
    __shared__ float tile[32][33];
    int k0 = blockIdx.y * 32, n0 = blockIdx.x * 32;
    int tx = threadIdx.x & 31, ty = threadIdx.x >> 5;
    for (int i = 0; i < 32; i += 8)
        tile[ty + i][tx] = W[(size_t)(k0 + ty + i) * ldin + n0 + tx];
    __syncthreads();
    for (int i = 0; i < 32; i += 8) {
        int n = n0 + ty + i, k = k0 + tx;
        float v = tile[tx][ty + i];
        __nv_bfloat16 h = __float2bfloat16_rn(v);
        Thi[(size_t)n * K + k] = h;
        Tlo[(size_t)n * K + k] = __float2bfloat16_rn(v - __bfloat162float(h));
    }
}

__device__ __forceinline__ void mma_bf16(float* c, const uint32_t* a,
                                         uint32_t b0, uint32_t b1) {
    asm volatile(
        "mma.sync.aligned.m16n8k16.row.col.f32.bf16.bf16.f32 "
        "{%0,%1,%2,%3}, {%4,%5,%6,%7}, {%8,%9}, {%0,%1,%2,%3};"
        : "+f"(c[0]), "+f"(c[1]), "+f"(c[2]), "+f"(c[3])
        : "r"(a[0]), "r"(a[1]), "r"(a[2]), "r"(a[3]), "r"(b0), "r"(b1));
}

// ---------------------------------------------------------------------------
// mma.sync split-bf16 GEMM (validated R10-R12)
// ---------------------------------------------------------------------------
#define GLDS 56
#define TILE_E (128 * GLDS)
#define GT_SMEM (2 * 4 * TILE_E * 2)

__device__ __forceinline__ void issue_chunk(
    __nv_bfloat16* st,
    const __nv_bfloat16* Ahi, const __nv_bfloat16* Alo,
    const __nv_bfloat16* Bhi, const __nv_bfloat16* Blo,
    int m0, int n0, int Ktot, int k0, int tid) {
    const __nv_bfloat16* srcs[4] = {Ahi, Alo, Bhi, Blo};
#pragma unroll
    for (int t = 0; t < 4; t++) {
        int rbase = (t < 2) ? m0 : n0;
        const __nv_bfloat16* gp = srcs[t];
#pragma unroll
        for (int i = 0; i < 2; i++) {
            int u = i * 256 + tid;
            int row = u >> 2;
            int koff = (u & 3) * 8;
            uint32_t d = smem_u32(st + t * TILE_E + row * GLDS + koff);
            const void* s = gp + (size_t)(rbase + row) * Ktot + k0 + koff;
            asm volatile("cp.async.ca.shared.global [%0], [%1], 16;"
                         :: "r"(d), "l"(s) : "memory");
        }
    }
    asm volatile("cp.async.commit_group;" ::: "memory");
}

__global__ void __launch_bounds__(256, 1)
gemmT_kernel(const __nv_bfloat16* __restrict__ Ahi, const __nv_bfloat16* __restrict__ Alo,
             const __nv_bfloat16* __restrict__ Bhi, const __nv_bfloat16* __restrict__ Blo,
             const float* __restrict__ bias, float* __restrict__ C,
             int Ktot, int Ncols) {
    extern __shared__ __nv_bfloat16 sm[];
    int tid = threadIdx.x, warp = tid >> 5, lane = tid & 31;
    int m0 = blockIdx.y << 7, n0 = blockIdx.x << 7;
    int wm = warp >> 2, wn = warp & 3;
    uint32_t sb = smem_u32(sm);

    float acc[4][4][4];
#pragma unroll
    for (int i = 0; i < 4; i++)
#pragma unroll
        for (int j = 0; j < 4; j++)
#pragma unroll
            for (int q = 0; q < 4; q++) acc[i][j][q] = 0.0f;

    int q4 = lane >> 3, r8 = lane & 7;
    int aro = (q4 & 1) * 8 + r8;
    int aco = (q4 >> 1) * 8;
    int bj = (lane & 15) >> 3;
    int bro = lane & 7;

    int nchunk = Ktot >> 5;
    issue_chunk(sm, Ahi, Alo, Bhi, Blo, m0, n0, Ktot, 0, tid);

    for (int ch = 0; ch < nchunk; ch++) {
        if (ch + 1 < nchunk) {
            issue_chunk(sm + ((ch + 1) & 1) * 4 * TILE_E,
                        Ahi, Alo, Bhi, Blo, m0, n0, Ktot, (ch + 1) << 5, tid);
            asm volatile("cp.async.wait_group 1;" ::: "memory");
        } else {
            asm volatile("cp.async.wait_group 0;" ::: "memory");
        }
        __syncthreads();

        uint32_t stb = sb + (uint32_t)((ch & 1) * 4 * TILE_E * 2);
#pragma unroll
        for (int s = 0; s < 2; s++) {
            uint32_t ah[4][4], al[4][4], bh[4][2], bl[4][2];
#pragma unroll
            for (int mi = 0; mi < 4; mi++) {
                uint32_t ad = stb +
                    (uint32_t)(((wm * 64 + mi * 16 + aro) * GLDS + s * 16 + aco) * 2);
                asm volatile(
                    "ldmatrix.sync.aligned.m8n8.x4.shared.b16 {%0,%1,%2,%3}, [%4];"
                    : "=r"(ah[mi][0]), "=r"(ah[mi][1]), "=r"(ah[mi][2]), "=r"(ah[mi][3])
                    : "r"(ad));
                asm volatile(
                    "ldmatrix.sync.aligned.m8n8.x4.shared.b16 {%0,%1,%2,%3}, [%4];"
                    : "=r"(al[mi][0]), "=r"(al[mi][1]), "=r"(al[mi][2]), "=r"(al[mi][3])
                    : "r"(ad + TILE_E * 2));
            }
#pragma unroll
            for (int ni = 0; ni < 4; ni++) {
                uint32_t bd = stb + (uint32_t)((2 * TILE_E +
                    (wn * 32 + ni * 8 + bro) * GLDS + s * 16 + bj * 8) * 2);
                asm volatile(
                    "ldmatrix.sync.aligned.m8n8.x2.shared.b16 {%0,%1}, [%2];"
                    : "=r"(bh[ni][0]), "=r"(bh[ni][1]) : "r"(bd));
                asm volatile(
                    "ldmatrix.sync.aligned.m8n8.x2.shared.b16 {%0,%1}, [%2];"
                    : "=r"(bl[ni][0]), "=r"(bl[ni][1]) : "r"(bd + TILE_E * 2));
            }
#pragma unroll
            for (int mi = 0; mi < 4; mi++)
#pragma unroll
                for (int ni = 0; ni < 4; ni++) {
                    mma_bf16(acc[mi][ni], ah[mi], bh[ni][0], bh[ni][1]);
                    mma_bf16(acc[mi][ni], ah[mi], bl[ni][0], bl[ni][1]);
                    mma_bf16(acc[mi][ni], al[mi], bh[ni][0], bh[ni][1]);
                }
        }
        __syncthreads();
    }

    int g = lane >> 2, t2 = (lane & 3) * 2;
#pragma unroll
    for (int mi = 0; mi < 4; mi++) {
        int mrow = m0 + wm * 64 + mi * 16 + g;
#pragma unroll
        for (int ni = 0; ni < 4; ni++) {
            int col = n0 + wn * 32 + ni * 8 + t2;
            float b0v = bias[col], b1v = bias[col + 1];
            float2 v0 = { acc[mi][ni][0] + b0v, acc[mi][ni][1] + b1v };
            float2 v1 = { acc[mi][ni][2] + b0v, acc[mi][ni][3] + b1v };
            *(float2*)&C[(size_t)mrow * Ncols + col] = v0;
            *(float2*)&C[(size_t)(mrow + 8) * Ncols + col] = v1;
        }
    }
}

// ---------------------------------------------------------------------------
// grid barrier
// ---------------------------------------------------------------------------
__device__ __forceinline__ void grid_barrier(unsigned expected) {
    __syncthreads();
    if (threadIdx.x == 0) {
        __threadfence();
        unsigned gen = *(volatile unsigned*)&g_bar_gen;
        unsigned a = atomicAdd(&g_bar_count, 1);
        if (a == expected - 1) {
            g_bar_count = 0;
            __threadfence();
            atomicAdd(&g_bar_gen, 1);
        } else {
            while (*(volatile unsigned*)&g_bar_gen == gen) { }
        }
        __threadfence();
    }
    __syncthreads();
}

// ---------------------------------------------------------------------------
// Tensorized persistent LSTM recurrence v3.
// - Weights persistent in SMEM (132 KB/CTA, loaded once)
// - 8 warps = 2(wm) x 4(kq K-split); warp tile 32x32 (N full slice)
//   -> LDSM per MAC cut 1.5x vs v2; zex has 4 partial buffers
// - A double-buffered cp.async, 64-k stages; each warp handles its 16-k slice
// ---------------------------------------------------------------------------
#define RLDS   72
#define RA_E   (64 * RLDS)              // elems per split tile (64 rows x 72)
#define RSTG_B (2 * RA_E * 2)           // 18432 bytes per stage (hi+lo)
#define ZEX_B  (2 * RSTG_B)             // 36864: zex region (4 buffers)
#define ZEX_STRIDE (64 * 33)            // floats per buffer
#define BW_B   (ZEX_B + 4 * ZEX_STRIDE * 4)  // 36864 + 33792 = 70656
#define BSTR   1032
#define BSPL_B (32 * BSTR * 2)          // 66048 bytes per weight split
#define RK_SMEM (BW_B + 2 * BSPL_B)     // 202752 bytes

__device__ __forceinline__ void rk_load_A(
    uint32_t sb, int stg,
    const __nv_bfloat16* abh, const __nv_bfloat16* abl, size_t rstr,
    int it, int tid) {
    uint32_t base = sb + (uint32_t)(stg * RSTG_B);
    int k0 = it * 64;
#pragma unroll
    for (int i = 0; i < 2; i++) {
        int u = i * 256 + tid;             // 0..511
        int row = u >> 3;                  // 0..63
        int seg = (u & 7) * 8;             // 0..56
        asm volatile("cp.async.ca.shared.global [%0], [%1], 16;"
            :: "r"(base + (uint32_t)((row * RLDS + seg) * 2)),
               "l"(abh + (size_t)row * rstr + k0 + seg) : "memory");
        asm volatile("cp.async.ca.shared.global [%0], [%1], 16;"
            :: "r"(base + (uint32_t)((RA_E + row * RLDS + seg) * 2)),
               "l"(abl + (size_t)row * rstr + k0 + seg) : "memory");
    }
    asm volatile("cp.async.commit_group;" ::: "memory");
}

__global__ void __launch_bounds__(256, 1)
lstm_mma_persistent(const float* __restrict__ state,       // [B,2MM] (c|h)
                    const __nv_bfloat16* __restrict__ Whh, // [G4 rows][MM k]
                    const __nv_bfloat16* __restrict__ Whl,
                    const __nv_bfloat16* __restrict__ h0h, // [B][MM]
                    const __nv_bfloat16* __restrict__ h0l,
                    const float* __restrict__ pre,         // [B][T][G4]
                    __nv_bfloat16* __restrict__ hsh,       // [B][T][MM]
                    __nv_bfloat16* __restrict__ hsl,
                    float* __restrict__ cfin, float* __restrict__ hfin) {
    extern __shared__ uint8_t smraw[];
    uint32_t sb = smem_u32(smraw);
    float* zex = (float*)(smraw + ZEX_B);

    int tid = threadIdx.x, lane = tid & 31, warp = tid >> 5;
    int wm = warp >> 2, kq = warp & 3;     // 2 x 4
    int mt0 = blockIdx.x * 8;

    // ---- preload recurrent weights into persistent SMEM (once) ----
    for (int i = tid; i < 4096; i += 256) {
        int cc = i >> 7, ch = i & 127;
        int n = (cc >> 3) * MM + mt0 + (cc & 7);
        uint32_t d = sb + BW_B + (uint32_t)((cc * BSTR + ch * 8) * 2);
        asm volatile("cp.async.ca.shared.global [%0], [%1], 16;"
            :: "r"(d), "l"(Whh + (size_t)n * MM + ch * 8) : "memory");
        asm volatile("cp.async.ca.shared.global [%0], [%1], 16;"
            :: "r"(d + BSPL_B), "l"(Whl + (size_t)n * MM + ch * 8) : "memory");
    }
    asm volatile("cp.async.commit_group;" ::: "memory");
    asm volatile("cp.async.wait_group 0;" ::: "memory");
    __syncthreads();

    // epilogue ownership: (b = tid/8 (+32), j = tid&7)
    int be = tid >> 3, je = tid & 7;
    float c0 = state[(size_t)be * (2 * MM) + mt0 + je];
    float c1 = state[(size_t)(be + 32) * (2 * MM) + mt0 + je];

    int aro = lane & 15, aco = (lane >> 4) * 8;
    int bro = lane & 7, bj = (lane & 15) >> 3;

    for (int t = 0; t < TT; t++) {
        const __nv_bfloat16 *abh, *abl;
        size_t rstr;
        if (t == 0) { abh = h0h; abl = h0l; rstr = MM; }
        else {
            abh = hsh + (size_t)(t - 1) * MM;
            abl = hsl + (size_t)(t - 1) * MM;
            rstr = (size_t)TT * MM;
        }

        float pv[8];
#pragma unroll
        for (int g = 0; g < 4; g++) {
            pv[g]     = pre[((size_t)be * TT + t) * G4 + g * MM + mt0 + je];
            pv[4 + g] = pre[((size_t)(be + 32) * TT + t) * G4 + g * MM + mt0 + je];
        }

        float acc[2][4][4];
#pragma unroll
        for (int mi = 0; mi < 2; mi++)
#pragma unroll
            for (int ni = 0; ni < 4; ni++)
#pragma unroll
                for (int q = 0; q < 4; q++) acc[mi][ni][q] = 0.0f;

        rk_load_A(sb, 0, abh, abl, rstr, 0, tid);
        for (int it = 0; it < 16; it++) {
            if (it + 1 < 16) {
                rk_load_A(sb, (it + 1) & 1, abh, abl, rstr, it + 1, tid);
                asm volatile("cp.async.wait_group 1;" ::: "memory");
            } else {
                asm volatile("cp.async.wait_group 0;" ::: "memory");
            }
            __syncthreads();

            uint32_t stb = sb + (uint32_t)((it & 1) * RSTG_B);
            // this warp's 16-k slice within the 64-k stage
            uint32_t ah[2][4], al[2][4];
#pragma unroll
            for (int mi = 0; mi < 2; mi++) {
                uint32_t ad = stb + (uint32_t)(((wm * 32 + mi * 16 + aro) * RLDS +
                                               kq * 16 + aco) * 2);
                asm volatile(
                    "ldmatrix.sync.aligned.m8n8.x4.shared.b16 {%0,%1,%2,%3}, [%4];"
                    : "=r"(ah[mi][0]), "=r"(ah[mi][1]), "=r"(ah[mi][2]), "=r"(ah[mi][3])
                    : "r"(ad));
                asm volatile(
                    "ldmatrix.sync.aligned.m8n8.x4.shared.b16 {%0,%1,%2,%3}, [%4];"
                    : "=r"(al[mi][0]), "=r"(al[mi][1]), "=r"(al[mi][2]), "=r"(al[mi][3])
                    : "r"(ad + RA_E * 2));
            }
#pragma unroll
            for (int ni = 0; ni < 4; ni++) {
                uint32_t bh0, bh1, bl0, bl1;
                uint32_t bd = sb + BW_B + (uint32_t)((
                    (ni * 8 + bro) * BSTR + it * 64 + kq * 16 + bj * 8) * 2);
                asm volatile(
                    "ldmatrix.sync.aligned.m8n8.x2.shared.b16 {%0,%1}, [%2];"
                    : "=r"(bh0), "=r"(bh1) : "r"(bd));
                asm volatile(
                    "ldmatrix.sync.aligned.m8n8.x2.shared.b16 {%0,%1}, [%2];"
                    : "=r"(bl0), "=r"(bl1) : "r"(bd + BSPL_B));
#pragma unroll
                for (int mi = 0; mi < 2; mi++) {
                    mma_bf16(acc[mi][ni], ah[mi], bh0, bh1);
                    mma_bf16(acc[mi][ni], ah[mi], bl0, bl1);
                    mma_bf16(acc[mi][ni], al[mi], bh0, bh1);
                }
            }
            __syncthreads();
        }

        // partial-z exchange: buffer per K-quarter
        float* zx = zex + kq * ZEX_STRIDE;
#pragma unroll
        for (int mi = 0; mi < 2; mi++)
#pragma unroll
            for (int ni = 0; ni < 4; ni++) {
                int r = wm * 32 + mi * 16 + (lane >> 2);
                int c = ni * 8 + (lane & 3) * 2;
                zx[r * 33 + c]           = acc[mi][ni][0];
                zx[r * 33 + c + 1]       = acc[mi][ni][1];
                zx[(r + 8) * 33 + c]     = acc[mi][ni][2];
                zx[(r + 8) * 33 + c + 1] = acc[mi][ni][3];
            }
        __syncthreads();

#pragma unroll
        for (int p = 0; p < 2; p++) {
            int b = be + p * 32;
            float zi = pv[p * 4 + 0], zj = pv[p * 4 + 1];
            float zf = pv[p * 4 + 2], zo = pv[p * 4 + 3];
#pragma unroll
            for (int q = 0; q < 4; q++) {
                const float* zq = zex + q * ZEX_STRIDE + b * 33;
                zi += zq[je];
                zj += zq[8 + je];
                zf += zq[16 + je];
                zo += zq[24 + je];
            }
            float fg = sigmoidf_(zf + 1.0f);   // FORGET_BIAS
            float ig = sigmoidf_(zi);
            float og = sigmoidf_(zo);
            float cv = (p ? c1 : c0) * fg + ig * tanhf(zj);
            if (p) c1 = cv; else c0 = cv;
            float hv = tanhf(cv) * og;
            size_t ha = ((size_t)b * TT + t) * MM + mt0 + je;
            __nv_bfloat16 hh = __float2bfloat16_rn(hv);
            hsh[ha] = hh;
            hsl[ha] = __float2bfloat16_rn(hv - __bfloat162float(hh));
            if (t == TT - 1) {
                cfin[(size_t)b * MM + mt0 + je] = cv;
                hfin[(size_t)b * MM + mt0 + je] = hv;
            }
        }
        grid_barrier(gridDim.x);
    }
}

// ---------------------------------------------------------------------------
__global__ void final_state_kernel(float* __restrict__ out) {
    int i = blockIdx.x * blockDim.x + threadIdx.x;
    if (i < 2 * BB * 2 * MM) {
        int l = i / (BB * 2 * MM);
        int r = i % (BB * 2 * MM);
        int b = r / (2 * MM);
        int mm = r % (2 * MM);
        float v = (mm < MM) ? g_cfin[l * BB * MM + b * MM + mm]
                            : g_hfin[l * BB * MM + b * MM + (mm - MM)];
        out[i] = v;
    }
}

// ---------------------------------------------------------------------------
extern "C" void kernel_launch(void* const* d_in, const int* in_sizes, int n_in,
                              void* d_out, int out_size) {
    const float* x      = (const float*)d_in[0];
    const float* state0 = (const float*)d_in[1];
    const float* state1 = (const float*)d_in[2];
    const float* W0     = (const float*)d_in[3];
    const float* b0     = (const float*)d_in[4];
    const float* W1     = (const float*)d_in[5];
    const float* b1     = (const float*)d_in[6];
    const float* W_out  = (const float*)d_in[7];
    const float* b_out  = (const float*)d_in[8];
    float* out = (float*)d_out;

    float *pre, *cfin, *hfin;
    cudaGetSymbolAddress((void**)&pre,  g_pre);
    cudaGetSymbolAddress((void**)&cfin, g_cfin);
    cudaGetSymbolAddress((void**)&hfin, g_hfin);
    __nv_bfloat16 *Ahi, *Alo, *h0h, *h0l;
    __nv_bfloat16 *Wt0h, *Wt0l, *Wt1h, *Wt1l, *WtOh, *WtOl;
    __nv_bfloat16 *Wh0h, *Wh0l, *Wh1h, *Wh1l;
    cudaGetSymbolAddress((void**)&Ahi,  g_Ahi);
    cudaGetSymbolAddress((void**)&Alo,  g_Alo);
    cudaGetSymbolAddress((void**)&h0h,  g_h0h);
    cudaGetSymbolAddress((void**)&h0l,  g_h0l);
    cudaGetSymbolAddress((void**)&Wt0h, g_Wt0hi);
    cudaGetSymbolAddress((void**)&Wt0l, g_Wt0lo);
    cudaGetSymbolAddress((void**)&Wt1h, g_Wt1hi);
    cudaGetSymbolAddress((void**)&Wt1l, g_Wt1lo);
    cudaGetSymbolAddress((void**)&WtOh, g_WtOhi);
    cudaGetSymbolAddress((void**)&WtOl, g_WtOlo);
    cudaGetSymbolAddress((void**)&Wh0h, g_Wh0hi);
    cudaGetSymbolAddress((void**)&Wh0l, g_Wh0lo);
    cudaGetSymbolAddress((void**)&Wh1h, g_Wh1hi);
    cudaGetSymbolAddress((void**)&Wh1l, g_Wh1lo);

    cudaFuncSetAttribute(gemmT_kernel,
                         cudaFuncAttributeMaxDynamicSharedMemorySize, GT_SMEM);
    cudaFuncSetAttribute(lstm_mma_persistent,
                         cudaFuncAttributeMaxDynamicSharedMemorySize, RK_SMEM);

    // weight preps (transpose + split)
    transpose_split_kernel<<<dim3(G4 / 32, VV / 32), 256>>>(W0, G4, Wt0h, Wt0l, VV, G4);
    transpose_split_kernel<<<dim3(G4 / 32, MM / 32), 256>>>(W1, G4, Wt1h, Wt1l, MM, G4);
    transpose_split_kernel<<<dim3(VV / 32, MM / 32), 256>>>(W_out, VV, WtOh, WtOl, MM, VV);
    transpose_split_kernel<<<dim3(G4 / 32, MM / 32), 256>>>(
        W0 + (size_t)VV * G4, G4, Wh0h, Wh0l, MM, G4);
    transpose_split_kernel<<<dim3(G4 / 32, MM / 32), 256>>>(
        W1 + (size_t)MM * G4, G4, Wh1h, Wh1l, MM, G4);

    // pre0 = x @ W0x + b0
    size_t nx = (size_t)BB * TT * VV;
    split_kernel<<<(unsigned)((nx + 255) / 256), 256>>>(x, Ahi, Alo, nx);
    gemmT_kernel<<<dim3(G4 / 128, (BB * TT) / 128), 256, GT_SMEM>>>(
        Ahi, Alo, Wt0h, Wt0l, b0, pre, VV, G4);

    // layer 0 recurrence (writes h0 splits into Ahi/Alo)
    split_state_h<<<(BB * MM + 255) / 256, 256>>>(state0, h0h, h0l);
    lstm_mma_persistent<<<128, 256, RK_SMEM>>>(
        state0, Wh0h, Wh0l, h0h, h0l, pre, Ahi, Alo, cfin, hfin);

    // pre1 = h0_seq @ W1x + b1
    gemmT_kernel<<<dim3(G4 / 128, (BB * TT) / 128), 256, GT_SMEM>>>(
        Ahi, Alo, Wt1h, Wt1l, b1, pre, MM, G4);

    // layer 1 recurrence
    split_state_h<<<(BB * MM + 255) / 256, 256>>>(state1, h0h, h0l);
    lstm_mma_persistent<<<128, 256, RK_SMEM>>>(
        state1, Wh1h, Wh1l, h0h, h0l, pre, Ahi, Alo,
        cfin + BB * MM, hfin + BB * MM);

    // outputs = h1_seq @ W_out + b_out
    gemmT_kernel<<<dim3(VV / 128, (BB * TT) / 128), 256, GT_SMEM>>>(
        Ahi, Alo, WtOh, WtOl, b_out, out, MM, VV);

    final_state_kernel<<<(2 * BB * 2 * MM + 255) / 256, 256>>>(
        out + (size_t)BB * TT * VV);
}